// round 2
// baseline (speedup 1.0000x reference)
#include <cuda_runtime.h>
#include <math.h>

#define NU 100000
#define NI 50000
#define NE 120000
#define NR 32
#define DM 64
#define NEDGE 1000000
#define NCF 1000000

#define SEG_U 120000           // user segment base in global key space
#define SEG_I 220000           // item segment base
#define NSEG 270000
#define SCAN_N 270001
#define SCAN_BLK 1024
#define SCAN_NBLK 264          // 264*1024 = 270336 >= 270001

// ---------------- scratch (device globals; no allocation allowed) ----------------
__device__ int   g_cnt[SCAN_NBLK * SCAN_BLK];
__device__ int   g_off[SCAN_NBLK * SCAN_BLK + 1];
__device__ int   g_cur[NSEG];
__device__ int   g_perm[NEDGE + 2 * NCF];
__device__ int   g_bsum[SCAN_BLK];
__device__ int   g_boff[SCAN_BLK];

__device__ float g_entA[NE * DM];
__device__ float g_entB[NE * DM];
__device__ float g_rel[NI * DM];
__device__ float g_u[NU * DM];
__device__ float g_ucf0[NU * DM];
__device__ float g_ucf1[NU * DM];
__device__ float g_icf0[NI * DM];
__device__ float g_icf1[NI * DM];
__device__ float g_p[NCF];
__device__ float g_pcf[NCF];

__device__ __forceinline__ float warpsum(float v) {
    #pragma unroll
    for (int o = 16; o; o >>= 1) v += __shfl_xor_sync(0xffffffffu, v, o);
    return v;
}
__device__ __forceinline__ float lrelu(float x) { return x > 0.f ? x : 0.01f * x; }
__device__ __forceinline__ float sigmoidf(float x) { return 1.f / (1.f + __expf(-x)); }

// ---------------- init: out = concat(entity, user, ucf, icf) ----------------
__global__ void k_init(const float* __restrict__ ue, const float* __restrict__ ee,
                       const float* __restrict__ cf, float* __restrict__ out) {
    const int total = (NE + NU + NU + NI) * DM;
    for (int i = blockIdx.x * blockDim.x + threadIdx.x; i < total; i += gridDim.x * blockDim.x) {
        float v;
        if (i < NE * DM)                   v = ee[i];
        else if (i < (NE + NU) * DM)       v = ue[i - NE * DM];
        else if (i < (NE + 2 * NU) * DM)   v = cf[i - (NE + NU) * DM];
        else                               v = cf[NU * DM + (i - (NE + 2 * NU) * DM)];
        out[i] = v;
    }
}

__global__ void k_zero() {
    for (int i = blockIdx.x * blockDim.x + threadIdx.x; i < SCAN_NBLK * SCAN_BLK;
         i += gridDim.x * blockDim.x) {
        g_cnt[i] = 0;
        if (i < NSEG) g_cur[i] = 0;
    }
}

__global__ void k_count(const int* __restrict__ heads, const int* __restrict__ imat) {
    for (int i = blockIdx.x * blockDim.x + threadIdx.x; i < NEDGE; i += gridDim.x * blockDim.x) {
        atomicAdd(&g_cnt[heads[i]], 1);
        atomicAdd(&g_cnt[SEG_U + imat[2 * i]], 1);
        atomicAdd(&g_cnt[SEG_I + imat[2 * i + 1]], 1);
    }
}

// ---------------- exclusive scan (3 phases) ----------------
__global__ void k_scan1() {
    __shared__ int sh[SCAN_BLK];
    int t = threadIdx.x;
    int i = blockIdx.x * SCAN_BLK + t;
    sh[t] = (i < SCAN_N) ? g_cnt[i] : 0;
    __syncthreads();
    for (int s = SCAN_BLK / 2; s > 0; s >>= 1) {
        if (t < s) sh[t] += sh[t + s];
        __syncthreads();
    }
    if (t == 0) g_bsum[blockIdx.x] = sh[0];
}
__global__ void k_scan2() {
    __shared__ int sh[SCAN_BLK];
    int t = threadIdx.x;
    int v = (t < SCAN_NBLK) ? g_bsum[t] : 0;
    sh[t] = v;
    __syncthreads();
    for (int d = 1; d < SCAN_BLK; d <<= 1) {
        int x = (t >= d) ? sh[t - d] : 0;
        __syncthreads();
        sh[t] += x;
        __syncthreads();
    }
    if (t < SCAN_NBLK) g_boff[t] = sh[t] - v;
}
__global__ void k_scan3() {
    __shared__ int sh[SCAN_BLK];
    int t = threadIdx.x;
    int i = blockIdx.x * SCAN_BLK + t;
    int v = (i < SCAN_N) ? g_cnt[i] : 0;
    sh[t] = v;
    __syncthreads();
    for (int d = 1; d < SCAN_BLK; d <<= 1) {
        int x = (t >= d) ? sh[t - d] : 0;
        __syncthreads();
        sh[t] += x;
        __syncthreads();
    }
    if (i < SCAN_N) g_off[i] = g_boff[blockIdx.x] + sh[t] - v;
}

__global__ void k_scatter(const int* __restrict__ heads, const int* __restrict__ imat) {
    for (int i = blockIdx.x * blockDim.x + threadIdx.x; i < NEDGE; i += gridDim.x * blockDim.x) {
        int h = heads[i];
        int p = g_off[h] + atomicAdd(&g_cur[h], 1);
        g_perm[p] = i;
        int r = SEG_U + imat[2 * i];
        p = g_off[r] + atomicAdd(&g_cur[r], 1);
        g_perm[p] = i;
        int c = SEG_I + imat[2 * i + 1];
        p = g_off[c] + atomicAdd(&g_cur[c], 1);
        g_perm[p] = i;
    }
}

// ---------------- entity aggregation + transform + norm + residual ----------------
__global__ void k_entity(const float* __restrict__ ext_ent, int hop,
                         const float* __restrict__ relw,
                         const float* __restrict__ W1, const float* __restrict__ b1,
                         const float* __restrict__ W2, const float* __restrict__ b2,
                         const int* __restrict__ tails, const int* __restrict__ etype,
                         float* __restrict__ out) {
    __shared__ float s_rel[NR * DM];
    __shared__ float sW1[DM * 65];
    __shared__ float sW2[DM * 65];
    __shared__ float sb1[DM], sb2[DM];
    int t = threadIdx.x;
    for (int i = t; i < NR * DM; i += blockDim.x) s_rel[i] = relw[i];
    for (int i = t; i < DM * DM; i += blockDim.x) {
        int d = i >> 6, k = i & 63;
        sW1[d * 65 + k] = W1[i];
        sW2[d * 65 + k] = W2[i];
    }
    if (t < DM) { sb1[t] = b1[t]; sb2[t] = b2[t]; }
    __syncthreads();

    const float* entin = hop ? g_entB : ext_ent;
    float* entout      = hop ? g_entA : g_entB;

    int lane = t & 31;
    int e = blockIdx.x * (blockDim.x >> 5) + (t >> 5);
    if (e >= NE) return;
    int p0 = g_off[e], p1 = g_off[e + 1];
    bool eItem = e < NI;

    float a10 = 0, a11 = 0, a20 = 0, a21 = 0, ar0 = 0, ar1 = 0;
    int nc = 0;
    for (int p = p0; p < p1; p++) {
        int eid = g_perm[p];
        int tl = tails[eid];
        int ty = etype[eid];
        float r0 = s_rel[ty * 64 + lane], r1 = s_rel[ty * 64 + 32 + lane];
        float t0 = entin[tl * 64 + lane], t1 = entin[tl * 64 + 32 + lane];
        bool cross = eItem != (tl < NI);
        if (cross) { a10 += t0 * r0; a11 += t1 * r1; nc++; }
        else       { a20 += t0 + r0; a21 += t1 + r1; }
        ar0 += r0; ar1 += r1;
    }
    int n = p1 - p0;
    float i1 = 1.f / fmaxf((float)nc, 1.f);
    float i2 = 1.f / fmaxf((float)(n - nc), 1.f);
    a10 *= i1; a11 *= i1; a20 *= i2; a21 *= i2;

    float o10 = sb1[lane], o11 = sb1[lane + 32];
    float o20 = sb2[lane], o21 = sb2[lane + 32];
    #pragma unroll
    for (int k = 0; k < 64; k++) {
        float a = __shfl_sync(0xffffffffu, (k < 32) ? a10 : a11, k & 31);
        o10 += a * sW1[lane * 65 + k];
        o11 += a * sW1[(lane + 32) * 65 + k];
    }
    #pragma unroll
    for (int k = 0; k < 64; k++) {
        float a = __shfl_sync(0xffffffffu, (k < 32) ? a20 : a21, k & 31);
        o20 += a * sW2[lane * 65 + k];
        o21 += a * sW2[(lane + 32) * 65 + k];
    }
    float v0 = 0.5f * (lrelu(o10) + lrelu(o20));
    float v1 = 0.5f * (lrelu(o11) + lrelu(o21));
    float ss = warpsum(v0 * v0 + v1 * v1);
    float inv = 1.f / fmaxf(sqrtf(ss), 1e-12f);
    v0 *= inv; v1 *= inv;
    entout[e * 64 + lane] = v0;
    entout[e * 64 + 32 + lane] = v1;
    out[e * 64 + lane] += v0;
    out[e * 64 + 32 + lane] += v1;
    if (eItem) {
        float dn = 1.f / fmaxf((float)n, 1.f);
        g_rel[e * 64 + lane] = ar0 * dn;
        g_rel[e * 64 + 32 + lane] = ar1 * dn;
    }
}

// ---------------- item aggregation (seg mean of ucf by col) ----------------
__global__ void k_item(const float* __restrict__ ext_ucf, int hop,
                       const int* __restrict__ imat, float* __restrict__ out) {
    const float* ucfin = hop ? g_ucf0 : ext_ucf;
    float* icfout      = hop ? g_icf1 : g_icf0;
    int t = threadIdx.x, lane = t & 31;
    int c = blockIdx.x * (blockDim.x >> 5) + (t >> 5);
    if (c >= NI) return;
    int p0 = g_off[SEG_I + c], p1 = g_off[SEG_I + c + 1];
    float a0 = 0, a1 = 0;
    for (int p = p0; p < p1; p++) {
        int pid = g_perm[p];
        int row = imat[2 * pid];
        a0 += ucfin[row * 64 + lane];
        a1 += ucfin[row * 64 + 32 + lane];
    }
    float dn = 1.f / fmaxf((float)(p1 - p0), 1.f);
    a0 *= dn; a1 *= dn;
    float ss = warpsum(a0 * a0 + a1 * a1);
    float inv = 1.f / fmaxf(sqrtf(ss), 1e-12f);
    a0 *= inv; a1 *= inv;
    icfout[c * 64 + lane] = a0;
    icfout[c * 64 + 32 + lane] = a1;
    const int ob = (NE + 2 * NU) * DM;
    out[ob + c * 64 + lane] += a0;
    out[ob + c * 64 + 32 + lane] += a1;
}

// ---------------- user CF iteration (whole softmax in-warp) ----------------
// NOTE: user segments occupy global CSR positions [NEDGE, NEDGE+NCF);
// g_p/g_pcf are indexed with (p - NEDGE).
__global__ void k_user(const float* __restrict__ ext_user, const float* __restrict__ ext_ucf,
                       const float* __restrict__ ext_ent, const float* __restrict__ ext_icf,
                       int hop, int iter, int final_iter,
                       const int* __restrict__ imat, float* __restrict__ out) {
    const float* kg     = hop ? g_entB : ext_ent;
    const float* icf    = hop ? g_icf0 : ext_icf;
    const float* usrc   = (hop == 0 && iter == 0) ? ext_user : g_u;
    float* udst         = g_u;
    const float* ucfsrc = (iter == 0) ? (hop ? g_ucf0 : ext_ucf) : (hop ? g_ucf1 : g_ucf0);
    float* ucfdst       = hop ? g_ucf1 : g_ucf0;

    int t = threadIdx.x, lane = t & 31;
    int u = blockIdx.x * (blockDim.x >> 5) + (t >> 5);
    if (u >= NU) return;
    int p0 = g_off[SEG_U + u], p1 = g_off[SEG_U + u + 1];
    if (p0 == p1) {
        udst[u * 64 + lane] = 0.f;   udst[u * 64 + 32 + lane] = 0.f;
        ucfdst[u * 64 + lane] = 0.f; ucfdst[u * 64 + 32 + lane] = 0.f;
        return;
    }
    float uv0 = usrc[u * 64 + lane], uv1 = usrc[u * 64 + 32 + lane];
    float cv0 = ucfsrc[u * 64 + lane], cv1 = ucfsrc[u * 64 + 32 + lane];

    // pass 1: sigmoid(dot) per pair, track max
    float mx = -1e30f, mxc = -1e30f;
    for (int p = p0; p < p1; p++) {
        int pid = g_perm[p];
        int col = imat[2 * pid + 1];
        const float* kr = kg + col * 64;
        const float* rr = g_rel + col * 64;
        const float* ir = icf + col * 64;
        float s  = uv0 * rr[lane] * kr[lane] + uv1 * rr[32 + lane] * kr[32 + lane];
        float sc = cv0 * ir[lane] + cv1 * ir[32 + lane];
        s = warpsum(s); sc = warpsum(sc);
        float pp = sigmoidf(s);
        float pc = sigmoidf(sc);
        if (lane == 0) { g_p[p - NEDGE] = pp; g_pcf[p - NEDGE] = pc; }
        mx = fmaxf(mx, pp); mxc = fmaxf(mxc, pc);
    }
    // pass 2: exp + sum (lane0 read/write, broadcast)
    float se = 0.f, sec = 0.f;
    for (int p = p0; p < p1; p++) {
        float e1 = 0.f, e2 = 0.f;
        if (lane == 0) {
            e1 = __expf(g_p[p - NEDGE] - mx);
            e2 = __expf(g_pcf[p - NEDGE] - mxc);
            g_p[p - NEDGE] = e1; g_pcf[p - NEDGE] = e2;
        }
        se  += __shfl_sync(0xffffffffu, e1, 0);
        sec += __shfl_sync(0xffffffffu, e2, 0);
    }
    float is = 1.f / se, isc = 1.f / sec;
    // pass 3: weighted accumulation (mask is provably always 1:
    //   |sigmoid(a)-sigmoid(b)| <= 0.232 < 0.6 for a,b in [0,1])
    float A0 = 0, A1 = 0, B0 = 0, B1 = 0;
    for (int p = p0; p < p1; p++) {
        int pid = g_perm[p];
        int col = imat[2 * pid + 1];
        float e1 = 0.f, e2 = 0.f;
        if (lane == 0) { e1 = g_p[p - NEDGE]; e2 = g_pcf[p - NEDGE]; }
        float pn = __shfl_sync(0xffffffffu, e1, 0) * is;
        float pc = __shfl_sync(0xffffffffu, e2, 0) * isc;
        A0 += kg[col * 64 + lane] * pn;
        A1 += kg[col * 64 + 32 + lane] * pn;
        B0 += icf[col * 64 + lane] * pc;
        B1 += icf[col * 64 + 32 + lane] * pc;
    }
    float ss = warpsum(A0 * A0 + A1 * A1);
    float inv = 1.f / fmaxf(sqrtf(ss), 1e-12f);
    A0 *= inv; A1 *= inv;
    ss = warpsum(B0 * B0 + B1 * B1);
    inv = 1.f / fmaxf(sqrtf(ss), 1e-12f);
    B0 *= inv; B1 *= inv;
    udst[u * 64 + lane] = A0;   udst[u * 64 + 32 + lane] = A1;
    ucfdst[u * 64 + lane] = B0; ucfdst[u * 64 + 32 + lane] = B1;
    if (final_iter) {
        const int ob1 = NE * DM;
        const int ob2 = (NE + NU) * DM;
        out[ob1 + u * 64 + lane] += A0;
        out[ob1 + u * 64 + 32 + lane] += A1;
        out[ob2 + u * 64 + lane] += B0;
        out[ob2 + u * 64 + 32 + lane] += B1;
    }
}

// ---------------- launch ----------------
extern "C" void kernel_launch(void* const* d_in, const int* in_sizes, int n_in,
                              void* d_out, int out_size) {
    const float* user_emb = (const float*)d_in[0];
    const float* entity_emb = (const float*)d_in[1];
    const float* emb_cf = (const float*)d_in[2];
    const float* relw = (const float*)d_in[3];
    const float* W1 = (const float*)d_in[4];
    const float* B1 = (const float*)d_in[5];
    const float* W2 = (const float*)d_in[6];
    const float* B2 = (const float*)d_in[7];
    const int* eidx = (const int*)d_in[8];       // (2, NEDGE)
    const int* etype = (const int*)d_in[9];
    const int* imat = (const int*)d_in[10];      // (NCF, 2)
    float* out = (float*)d_out;

    const int* heads = eidx;
    const int* tails = eidx + NEDGE;
    const float* ucf_ext = emb_cf;               // first NU rows
    const float* icf_ext = emb_cf + NU * DM;     // last NI rows

    k_init<<<2048, 256>>>(user_emb, entity_emb, emb_cf, out);
    k_zero<<<1056, 256>>>();
    k_count<<<3907, 256>>>(heads, imat);
    k_scan1<<<SCAN_NBLK, SCAN_BLK>>>();
    k_scan2<<<1, SCAN_BLK>>>();
    k_scan3<<<SCAN_NBLK, SCAN_BLK>>>();
    k_scatter<<<3907, 256>>>(heads, imat);

    for (int h = 0; h < 2; h++) {
        k_entity<<<NE / 8, 256>>>(entity_emb, h, relw,
                                  W1 + h * DM * DM, B1 + h * DM,
                                  W2 + h * DM * DM, B2 + h * DM,
                                  tails, etype, out);
        k_item<<<NI / 8, 256>>>(ucf_ext, h, imat, out);
        for (int it = 0; it < 3; it++) {
            k_user<<<NU / 8, 256>>>(user_emb, ucf_ext, entity_emb, icf_ext,
                                    h, it, it == 2 ? 1 : 0, imat, out);
        }
    }
    (void)in_sizes; (void)n_in; (void)out_size;
}